// round 2
// baseline (speedup 1.0000x reference)
#include <cuda_runtime.h>
#include <cuda_bf16.h>

// GRU encoder: B=512, T=128, V=128, E=512, H=512, L=2
// out = [ states[T, L, B, H] , h_final[L, B, H] ]  (h_final == states[T-1])
//
// Strategy (R1 baseline): fused fp32 GRU-cell kernel, one launch per superstep t,
// computing layer0 @ step t and layer1 @ step t-1 concurrently (layer pipeline lag),
// 129 launches total. Hidden states are read from / written to the states region
// of d_out itself, so no scratch is needed.

namespace {

constexpr int B_ = 512;
constexpr int T_ = 128;
constexpr int E_ = 512;
constexpr int H_ = 512;
constexpr int L_ = 2;
constexpr int HG = 3 * H_;   // 1536

constexpr int BT = 64;   // batch tile per CTA
constexpr int JT = 32;   // hidden-unit tile per CTA
constexpr int KT = 32;   // K tile
constexpr int NC = 96;   // 3 gates * JT columns

// smem plan (48KB, exactly at the static limit):
//   phase A (GEMM passes): xs[KT][BT] (2048 f) + ws[KT][NC] (3072 f) = 20KB
//   phase B (gate math)  : sgi[BT][NC] (6144 f) + sgh[BT][NC] (6144 f) = 48KB
// Phase B overlays phase A (accumulators live in registers in between).

__global__ __launch_bounds__(256, 2)
void gru_cell(const int*   __restrict__ input,     // [B, T]
              const float* __restrict__ h0init,    // [L, B, H]
              const float* __restrict__ emb,       // [V, E]
              const float* __restrict__ w_ih,      // [L, 3H, E]
              const float* __restrict__ w_hh,      // [L, 3H, H]
              const float* __restrict__ b_ih,      // [L, 3H]
              const float* __restrict__ b_hh,      // [L, 3H]
              float*       __restrict__ out,
              int t, int write_final)
{
    const int layer = blockIdx.z;
    const int s = (layer == 0) ? t : t - 1;   // which time step this layer computes
    if (s < 0 || s >= T_) return;

    const int jbase = blockIdx.x * JT;
    const int bbase = blockIdx.y * BT;
    const int tid = threadIdx.x;
    const int tx = tid & 15;    // column group (6 cols each)
    const int ty = tid >> 4;    // row group (4 rows each)

    __shared__ float smem[12288];   // 48KB
    float (*xs)[BT]  = (float (*)[BT])(smem);            // [KT][BT]
    float (*ws)[NC]  = (float (*)[NC])(smem + KT * BT);  // [KT][NC]
    float (*sgi)[NC] = (float (*)[NC])(smem);            // [BT][NC]
    float (*sgh)[NC] = (float (*)[NC])(smem + BT * NC);  // [BT][NC]

    const float* wsrc_i = w_ih + (size_t)layer * HG * E_;
    const float* wsrc_h = w_hh + (size_t)layer * HG * H_;

    // x source for the gi pass
    const float* xbase = (layer == 0)
        ? emb
        : (out + (size_t)(s * L_ + 0) * B_ * H_);         // h0 at step s
    // previous hidden state for this layer
    const float* hprev = (s == 0)
        ? (h0init + (size_t)layer * B_ * H_)
        : (out + (size_t)((s - 1) * L_ + layer) * B_ * H_);

    float acc[2][4][6];
    #pragma unroll
    for (int p = 0; p < 2; p++)
        #pragma unroll
        for (int i = 0; i < 4; i++)
            #pragma unroll
            for (int j = 0; j < 6; j++)
                acc[p][i][j] = 0.0f;

    // pass 0: gi = x @ Wi^T ; pass 1: gh = h_prev @ Wh^T   (K = 512 both)
    #pragma unroll
    for (int pass = 0; pass < 2; pass++) {
        const float* wsrc = pass ? wsrc_h : wsrc_i;
        for (int k0 = 0; k0 < 512; k0 += KT) {
            // --- load x tile (transposed: xs[k][b]), 512 float4s ---
            #pragma unroll
            for (int it = 0; it < 2; it++) {
                int idx = tid + it * 256;
                int b   = idx & 63;
                int k4  = idx >> 6;         // 0..7
                const float* rowp;
                if (pass == 0) {
                    if (layer == 0) {
                        int tok = input[(size_t)(bbase + b) * T_ + s];
                        rowp = emb + (size_t)tok * E_;
                    } else {
                        rowp = xbase + (size_t)(bbase + b) * H_;
                    }
                } else {
                    rowp = hprev + (size_t)(bbase + b) * H_;
                }
                float4 v = *(const float4*)(rowp + k0 + k4 * 4);
                xs[k4 * 4 + 0][b] = v.x;
                xs[k4 * 4 + 1][b] = v.y;
                xs[k4 * 4 + 2][b] = v.z;
                xs[k4 * 4 + 3][b] = v.w;
            }
            // --- load W tile (transposed: ws[k][c]), 768 float4s ---
            #pragma unroll
            for (int it = 0; it < 3; it++) {
                int idx = tid + it * 256;
                int c   = idx % 96;
                int k4  = idx / 96;         // 0..7
                int g   = c >> 5;
                int jj  = c & 31;
                int m   = g * H_ + jbase + jj;
                float4 v = *(const float4*)(wsrc + (size_t)m * 512 + k0 + k4 * 4);
                ws[k4 * 4 + 0][c] = v.x;
                ws[k4 * 4 + 1][c] = v.y;
                ws[k4 * 4 + 2][c] = v.z;
                ws[k4 * 4 + 3][c] = v.w;
            }
            __syncthreads();
            #pragma unroll
            for (int k = 0; k < KT; k++) {
                float4 a  = *(const float4*)&xs[k][ty * 4];
                float2 w0 = *(const float2*)&ws[k][tx * 6 + 0];
                float2 w1 = *(const float2*)&ws[k][tx * 6 + 2];
                float2 w2 = *(const float2*)&ws[k][tx * 6 + 4];
                float av[4] = {a.x, a.y, a.z, a.w};
                float wv[6] = {w0.x, w0.y, w1.x, w1.y, w2.x, w2.y};
                #pragma unroll
                for (int i = 0; i < 4; i++)
                    #pragma unroll
                    for (int j = 0; j < 6; j++)
                        acc[pass][i][j] = fmaf(av[i], wv[j], acc[pass][i][j]);
            }
            __syncthreads();
        }
    }

    // --- dump accumulators to smem (overlays the GEMM tiles) ---
    #pragma unroll
    for (int i = 0; i < 4; i++)
        #pragma unroll
        for (int j = 0; j < 6; j++) {
            sgi[ty * 4 + i][tx * 6 + j] = acc[0][i][j];
            sgh[ty * 4 + i][tx * 6 + j] = acc[1][i][j];
        }
    __syncthreads();

    // --- gate math + store ---
    float* hdst = out + (size_t)(s * L_ + layer) * B_ * H_;
    float* fdst = (write_final && s == T_ - 1)
        ? (out + (size_t)T_ * L_ * B_ * H_ + (size_t)layer * B_ * H_)
        : nullptr;
    const float* bi = b_ih + (size_t)layer * HG;
    const float* bh = b_hh + (size_t)layer * HG;

    #pragma unroll
    for (int it = 0; it < 8; it++) {
        int e  = tid + it * 256;
        int jj = e & 31;
        int b  = e >> 5;            // 0..63
        int gb = bbase + b;
        int gj = jbase + jj;
        float gir = sgi[b][jj]      + bi[gj];
        float giz = sgi[b][32 + jj] + bi[H_ + gj];
        float gin = sgi[b][64 + jj] + bi[2 * H_ + gj];
        float ghr = sgh[b][jj]      + bh[gj];
        float ghz = sgh[b][32 + jj] + bh[H_ + gj];
        float ghn = sgh[b][64 + jj] + bh[2 * H_ + gj];
        float hp  = hprev[(size_t)gb * H_ + gj];
        float r = 1.0f / (1.0f + expf(-(gir + ghr)));
        float z = 1.0f / (1.0f + expf(-(giz + ghz)));
        float n = tanhf(gin + r * ghn);
        float h = (1.0f - z) * n + z * hp;
        hdst[(size_t)gb * H_ + gj] = h;
        if (fdst) fdst[(size_t)gb * H_ + gj] = h;
    }
}

} // namespace

extern "C" void kernel_launch(void* const* d_in, const int* in_sizes, int n_in,
                              void* d_out, int out_size) {
    const int*   input = (const int*)  d_in[0];
    const float* h0    = (const float*)d_in[1];
    const float* emb   = (const float*)d_in[2];
    const float* w_ih  = (const float*)d_in[3];
    const float* w_hh  = (const float*)d_in[4];
    const float* b_ih  = (const float*)d_in[5];
    const float* b_hh  = (const float*)d_in[6];
    float* out = (float*)d_out;

    // Write h_final region only if the output buffer includes it.
    const long long states_elems = (long long)T_ * L_ * B_ * H_;
    const int write_final = ((long long)out_size >= states_elems + (long long)L_ * B_ * H_) ? 1 : 0;

    dim3 grid(H_ / JT, B_ / BT, L_);   // (16, 8, 2)
    for (int t = 0; t <= T_; t++) {    // 129 supersteps (layer pipeline lag of 1)
        gru_cell<<<grid, 256>>>(input, h0, emb, w_ih, w_hh, b_ih, b_hh, out, t, write_final);
    }
}

// round 4
// speedup vs baseline: 5.4176x; 5.4176x over previous
#include <cuda_runtime.h>
#include <cuda_bf16.h>
#include <cstdint>

// GRU encoder B=512 T=128 E=H=512 L=2 — warp-MMA (HMMA bf16) hi/lo 3-pass pipeline.
// tcgen05 is unavailable under this harness's compute_103 virtual arch, so we use
// mma.sync.m16n8k16 bf16 (sm_80+ PTX) which ptxas accepts for sm_103.
// Per superstep t: gemm_step computes gh0(t), gi1(t-1), gh1(t-1); gate_step does the
// GRU gate math (layer0 input proj gathered from precomputed exact-fp32 P = emb@Wi0^T)
// and emits next-step bf16 hi/lo hidden-state operands.

namespace {

constexpr int B_ = 512, T_ = 128, H_ = 512, L_ = 2;
constexpr int NG = 1536;                  // 3*H
constexpr size_t BH  = (size_t)B_ * H_;
constexpr size_t BNG = (size_t)B_ * NG;
constexpr size_t WSZ = (size_t)NG * 512;  // one weight matrix
constexpr int MT = 128, NT = 128, KC = 64;
constexpr int NITER = 512 / KC;           // 8

constexpr int TSZ = 128 * KC * 2;               // one tile (hi or lo): 16384 B
constexpr int STAGE_BYTES = 4 * TSZ;            // Ahi|Alo|Bhi|Blo = 65536
constexpr int SMEM_ALLOC = 2 * STAGE_BYTES;     // 131072

__device__ __align__(256) float g_scr[3 * BNG];          // gh0 | gi1 | gh1
__device__ __align__(256) float g_P[128 * NG];           // emb @ Wi0^T (exact fp32)
__device__ __align__(256) __nv_bfloat16 g_Whi[3 * WSZ];  // Wh0 | Wi1 | Wh1 (hi)
__device__ __align__(256) __nv_bfloat16 g_Wlo[3 * WSZ];
__device__ __align__(256) __nv_bfloat16 g_Ahi[2 * BH];   // per-layer hidden (hi)
__device__ __align__(256) __nv_bfloat16 g_Alo[2 * BH];

__device__ __forceinline__ uint32_t s2u(const void* p) {
    uint32_t a;
    asm("{ .reg .u64 t; cvta.to.shared.u64 t, %1; cvt.u32.u64 %0, t; }" : "=r"(a) : "l"(p));
    return a;
}
__device__ __forceinline__ uint32_t sw128(uint32_t b) { return b ^ ((b >> 3) & 0x70); }
__device__ __forceinline__ void cp16(uint32_t dst, const void* src) {
    asm volatile("cp.async.cg.shared.global [%0], [%1], 16;" :: "r"(dst), "l"(src));
}
__device__ __forceinline__ void ldsm4(uint32_t* r, uint32_t addr) {
    asm volatile("ldmatrix.sync.aligned.m8n8.x4.shared.b16 {%0,%1,%2,%3}, [%4];"
                 : "=r"(r[0]), "=r"(r[1]), "=r"(r[2]), "=r"(r[3]) : "r"(addr));
}
__device__ __forceinline__ void mma16816(float* c, const uint32_t* a, const uint32_t* b) {
    asm volatile(
        "mma.sync.aligned.m16n8k16.row.col.f32.bf16.bf16.f32 "
        "{%0,%1,%2,%3}, {%4,%5,%6,%7}, {%8,%9}, {%0,%1,%2,%3};"
        : "+f"(c[0]), "+f"(c[1]), "+f"(c[2]), "+f"(c[3])
        : "r"(a[0]), "r"(a[1]), "r"(a[2]), "r"(a[3]), "r"(b[0]), "r"(b[1]));
}

// ============================ GEMM ============================
// job0: gh0 = h0(t-1) @ Wh0^T | job1: gi1 = h0(t-1) @ Wi1^T | job2: gh1 = h1(t-2) @ Wh1^T
__global__ void __launch_bounds__(256, 1) gemm_step(int t) {
    const int job = blockIdx.z;
    if (job == 0) { if (t >= T_) return; } else { if (t < 1) return; }

    const int a_sel = (job == 2) ? 1 : 0;
    const __nv_bfloat16* __restrict__ Ahi = g_Ahi + (size_t)a_sel * BH;
    const __nv_bfloat16* __restrict__ Alo = g_Alo + (size_t)a_sel * BH;
    const __nv_bfloat16* __restrict__ Bhi = g_Whi + (size_t)job * WSZ;
    const __nv_bfloat16* __restrict__ Blo = g_Wlo + (size_t)job * WSZ;
    float* __restrict__ dst = g_scr + (size_t)job * BNG;

    const int m0 = blockIdx.y * MT, n0 = blockIdx.x * NT;
    const int tid = threadIdx.x, wid = tid >> 5, lane = tid & 31;
    const int warp_m = wid & 3, warp_n = wid >> 2;   // 4 x 2 warps, warp tile 32x64

    extern __shared__ char smraw[];
    const uint32_t smb = s2u(smraw);

    auto load_stage = [&](int s, int k0) {
        const uint32_t st = smb + s * STAGE_BYTES;
        #pragma unroll
        for (int i = 0; i < 4; i++) {
            int c = tid + i * 256;            // 0..1023 chunks per tile
            int row = c >> 3, col = c & 7;
            uint32_t off = sw128((uint32_t)(row * 128 + col * 16));
            size_t ga = (size_t)(m0 + row) * 512 + k0 + col * 8;
            size_t gb = (size_t)(n0 + row) * 512 + k0 + col * 8;
            cp16(st + off,           Ahi + ga);
            cp16(st + TSZ + off,     Alo + ga);
            cp16(st + 2 * TSZ + off, Bhi + gb);
            cp16(st + 3 * TSZ + off, Blo + gb);
        }
        asm volatile("cp.async.commit_group;");
    };

    load_stage(0, 0);
    load_stage(1, KC);

    // lane-derived ldmatrix row/col selectors
    const int aRow  = warp_m * 32 + (lane & 15);
    const int aKsel = ((lane >> 4) & 1) * 16;                    // bytes
    const int bRow  = warp_n * 64 + ((lane >> 4) & 1) * 8 + (lane & 7);
    const int bKsel = ((lane >> 3) & 1) * 16;                    // bytes

    float acc[2][8][4];
    #pragma unroll
    for (int mi = 0; mi < 2; mi++)
        #pragma unroll
        for (int ni = 0; ni < 8; ni++)
            #pragma unroll
            for (int q = 0; q < 4; q++) acc[mi][ni][q] = 0.0f;

    for (int j = 0; j < NITER; j++) {
        if (j < NITER - 1) asm volatile("cp.async.wait_group 1;");
        else               asm volatile("cp.async.wait_group 0;");
        __syncthreads();
        const uint32_t st = smb + (j & 1) * STAGE_BYTES;

        #pragma unroll
        for (int ks = 0; ks < KC / 16; ks++) {
            uint32_t ah[2][4], al[2][4], bh[4][4], bl[4][4];
            #pragma unroll
            for (int mi = 0; mi < 2; mi++) {
                uint32_t off = sw128((uint32_t)((aRow + mi * 16) * 128 + ks * 32 + aKsel));
                ldsm4(ah[mi], st + off);
                ldsm4(al[mi], st + TSZ + off);
            }
            #pragma unroll
            for (int g = 0; g < 4; g++) {
                uint32_t off = sw128((uint32_t)((bRow + g * 16) * 128 + ks * 32 + bKsel));
                ldsm4(bh[g], st + 2 * TSZ + off);
                ldsm4(bl[g], st + 3 * TSZ + off);
            }
            #pragma unroll
            for (int mi = 0; mi < 2; mi++)
                #pragma unroll
                for (int ni = 0; ni < 8; ni++) {
                    const uint32_t* bhp = &bh[ni >> 1][(ni & 1) * 2];
                    const uint32_t* blp = &bl[ni >> 1][(ni & 1) * 2];
                    mma16816(acc[mi][ni], ah[mi], bhp);
                    mma16816(acc[mi][ni], ah[mi], blp);
                    mma16816(acc[mi][ni], al[mi], bhp);
                }
        }
        if (j + 2 < NITER) {
            __syncthreads();                   // all warps done reading this buffer
            load_stage(j & 1, (j + 2) * KC);
        }
    }

    // epilogue: fragment scatter directly to fp32 scratch
    #pragma unroll
    for (int mi = 0; mi < 2; mi++) {
        int row = m0 + warp_m * 32 + mi * 16 + (lane >> 2);
        #pragma unroll
        for (int ni = 0; ni < 8; ni++) {
            int col = n0 + warp_n * 64 + ni * 8 + (lane & 3) * 2;
            *(float2*)(dst + (size_t)row * NG + col) =
                make_float2(acc[mi][ni][0], acc[mi][ni][1]);
            *(float2*)(dst + (size_t)(row + 8) * NG + col) =
                make_float2(acc[mi][ni][2], acc[mi][ni][3]);
        }
    }
}

// ============================ gates ============================
__global__ void __launch_bounds__(256) gate_step(
        float* __restrict__ out, const int* __restrict__ input,
        const float* __restrict__ h0init,
        const float* __restrict__ b_ih, const float* __restrict__ b_hh,
        int t, int write_final) {
    const int layer = blockIdx.y;
    const int s = (layer == 0) ? t : t - 1;
    if (s < 0 || s >= T_) return;

    const int e4 = blockIdx.x * 256 + threadIdx.x;   // 65536 float4 per layer
    const int b = e4 >> 7;
    const int h = (e4 & 127) * 4;

    float4 gi_r, gi_z, gi_n;
    if (layer == 0) {
        const float* P = g_P + (size_t)input[b * T_ + s] * NG;
        gi_r = *(const float4*)(P + h);
        gi_z = *(const float4*)(P + 512 + h);
        gi_n = *(const float4*)(P + 1024 + h);
    } else {
        const float* G = g_scr + BNG + (size_t)b * NG;   // gi1
        gi_r = *(const float4*)(G + h);
        gi_z = *(const float4*)(G + 512 + h);
        gi_n = *(const float4*)(G + 1024 + h);
    }
    const float* GH = g_scr + (layer == 0 ? (size_t)0 : 2 * BNG) + (size_t)b * NG;
    float4 gh_r = *(const float4*)(GH + h);
    float4 gh_z = *(const float4*)(GH + 512 + h);
    float4 gh_n = *(const float4*)(GH + 1024 + h);

    const float* hp_ptr = (s == 0) ? (h0init + (size_t)layer * BH)
                                   : (out + (size_t)((s - 1) * L_ + layer) * BH);
    float4 hp = *(const float4*)(hp_ptr + (size_t)b * H_ + h);

    const float* bi = b_ih + layer * NG;
    const float* bh = b_hh + layer * NG;
    float4 bir = *(const float4*)(bi + h), biz = *(const float4*)(bi + 512 + h),
           bin = *(const float4*)(bi + 1024 + h);
    float4 bhr = *(const float4*)(bh + h), bhz = *(const float4*)(bh + 512 + h),
           bhn = *(const float4*)(bh + 1024 + h);

    float hv[4];
    #pragma unroll
    for (int i = 0; i < 4; i++) {
        float r = 1.0f / (1.0f + expf(-((&gi_r.x)[i] + (&bir.x)[i] + (&gh_r.x)[i] + (&bhr.x)[i])));
        float z = 1.0f / (1.0f + expf(-((&gi_z.x)[i] + (&biz.x)[i] + (&gh_z.x)[i] + (&bhz.x)[i])));
        float n = tanhf((&gi_n.x)[i] + (&bin.x)[i] + r * ((&gh_n.x)[i] + (&bhn.x)[i]));
        hv[i] = (1.0f - z) * n + z * (&hp.x)[i];
    }

    const size_t eoff = (size_t)b * H_ + h;
    *(float4*)(out + (size_t)(s * L_ + layer) * BH + eoff) =
        make_float4(hv[0], hv[1], hv[2], hv[3]);

    __nv_bfloat16* ah = g_Ahi + (size_t)layer * BH + eoff;
    __nv_bfloat16* al = g_Alo + (size_t)layer * BH + eoff;
    #pragma unroll
    for (int i = 0; i < 4; i++) {
        __nv_bfloat16 hi = __float2bfloat16(hv[i]);
        ah[i] = hi;
        al[i] = __float2bfloat16(hv[i] - __bfloat162float(hi));
    }

    if (write_final && s == T_ - 1)
        *(float4*)(out + (size_t)T_ * L_ * BH + (size_t)layer * BH + eoff) =
            make_float4(hv[0], hv[1], hv[2], hv[3]);
}

// ============================ prep ============================
__global__ void __launch_bounds__(256) prep_P(const float* __restrict__ emb,
                                              const float* __restrict__ w_ih) {
    // grid (NG/64, 128/32): P[v][n] = sum_k emb[v][k] * Wi0[n][k]  (exact fp32)
    const int n = blockIdx.x * 64 + (threadIdx.x & 63);
    const int vl = (threadIdx.x >> 6) * 8;
    __shared__ float es[64][33];
    float acc[8] = {};
    for (int k0 = 0; k0 < 512; k0 += 64) {
        __syncthreads();
        #pragma unroll
        for (int i = 0; i < 2; i++) {
            int lin = threadIdx.x + i * 256;
            int vv = lin >> 4, k4 = lin & 15;
            float4 e = *(const float4*)(emb + (size_t)(blockIdx.y * 32 + vv) * 512 + k0 + k4 * 4);
            es[k4 * 4 + 0][vv] = e.x; es[k4 * 4 + 1][vv] = e.y;
            es[k4 * 4 + 2][vv] = e.z; es[k4 * 4 + 3][vv] = e.w;
        }
        __syncthreads();
        const float* wp = w_ih + (size_t)n * 512 + k0;
        #pragma unroll 16
        for (int kk = 0; kk < 64; kk++) {
            float wv = wp[kk];
            #pragma unroll
            for (int j = 0; j < 8; j++) acc[j] = fmaf(wv, es[kk][vl + j], acc[j]);
        }
    }
    for (int j = 0; j < 8; j++)
        g_P[(size_t)(blockIdx.y * 32 + vl + j) * NG + n] = acc[j];
}

__global__ void __launch_bounds__(256) prep_W(const float* __restrict__ w_ih,
                                              const float* __restrict__ w_hh) {
    size_t e4 = ((size_t)blockIdx.x * 256 + threadIdx.x) * 4;   // over 3*WSZ
    size_t job = e4 / WSZ, off = e4 % WSZ;
    const float* src = (job == 0) ? (w_hh + off)
                     : (job == 1) ? (w_ih + WSZ + off) : (w_hh + WSZ + off);
    float4 v = *(const float4*)src;
    union { __nv_bfloat16 b[4]; uint2 u; } hi, lo;
    float f[4] = {v.x, v.y, v.z, v.w};
    #pragma unroll
    for (int i = 0; i < 4; i++) {
        hi.b[i] = __float2bfloat16(f[i]);
        lo.b[i] = __float2bfloat16(f[i] - __bfloat162float(hi.b[i]));
    }
    *(uint2*)(g_Whi + e4) = hi.u;
    *(uint2*)(g_Wlo + e4) = lo.u;
}

__global__ void __launch_bounds__(256) prep_A(const float* __restrict__ h0) {
    size_t e4 = ((size_t)blockIdx.x * 256 + threadIdx.x) * 4;   // over 2*BH
    float4 v = *(const float4*)(h0 + e4);
    union { __nv_bfloat16 b[4]; uint2 u; } hi, lo;
    float f[4] = {v.x, v.y, v.z, v.w};
    #pragma unroll
    for (int i = 0; i < 4; i++) {
        hi.b[i] = __float2bfloat16(f[i]);
        lo.b[i] = __float2bfloat16(f[i] - __bfloat162float(hi.b[i]));
    }
    *(uint2*)(g_Ahi + e4) = hi.u;
    *(uint2*)(g_Alo + e4) = lo.u;
}

} // namespace

extern "C" void kernel_launch(void* const* d_in, const int* in_sizes, int n_in,
                              void* d_out, int out_size) {
    const int*   input = (const int*)  d_in[0];
    const float* h0    = (const float*)d_in[1];
    const float* emb   = (const float*)d_in[2];
    const float* w_ih  = (const float*)d_in[3];
    const float* w_hh  = (const float*)d_in[4];
    const float* b_ih  = (const float*)d_in[5];
    const float* b_hh  = (const float*)d_in[6];
    float* out = (float*)d_out;

    const long long states_elems = (long long)T_ * L_ * B_ * H_;
    const int write_final =
        ((long long)out_size >= states_elems + (long long)L_ * B_ * H_) ? 1 : 0;

    cudaFuncSetAttribute(gemm_step, cudaFuncAttributeMaxDynamicSharedMemorySize, SMEM_ALLOC);

    prep_W<<<(int)(3 * WSZ / 4 / 256), 256>>>(w_ih, w_hh);
    prep_A<<<(int)(2 * BH / 4 / 256), 256>>>(h0);
    prep_P<<<dim3(NG / 64, 4), 256>>>(emb, w_ih);

    for (int t = 0; t <= T_; t++) {
        gemm_step<<<dim3(NG / NT, B_ / MT, 3), 256, SMEM_ALLOC>>>(t);
        gate_step<<<dim3(256, 2), 256>>>(out, input, h0, b_ih, b_hh, t, write_final);
    }
}